// round 7
// baseline (speedup 1.0000x reference)
#include <cuda_runtime.h>
#include <cuda_bf16.h>
#include <math_constants.h>
#include <cstdint>

// Problem constants (z: 32*2048*64 fp32, codebook: 1024*64 fp32)
#define N_VEC   65536
#define E_DIM   64
#define N_CODE  1024
#define ELEMS   (N_VEC * E_DIM)
#define CAP     64
#define SCALE_E 130048.0f        // 127 * 1024

// ---------------------------------------------------------------------------
// Global scratch (module globals; no runtime allocation)
// ---------------------------------------------------------------------------
__device__ float    g_cc[N_CODE];
__device__ uint32_t g_cb_i8[N_CODE * 16];    // packed int8 codebook (64 B/code)
__device__ int      g_idx[N_VEC];
__device__ int      g_counts[N_CODE];
__device__ float    g_sse_part[8192];
__device__ int      g_ccount[N_VEC];
__device__ int      g_over[N_VEC];
__device__ int      g_cand[N_VEC * CAP];

// ---------------------------------------------------------------------------
// helpers
// ---------------------------------------------------------------------------
__device__ __forceinline__ int dp4a(uint32_t a, uint32_t b, int c) {
    int d;
    asm("dp4a.s32.s32 %0, %1, %2, %3;" : "=r"(d) : "r"(a), "r"(b), "r"(c));
    return d;
}

__device__ __forceinline__ uint32_t pack4(int a, int b, int c, int d) {
    return (uint32_t)(a & 0xFF) | ((uint32_t)(b & 0xFF) << 8) |
           ((uint32_t)(c & 0xFF) << 16) | ((uint32_t)(d & 0xFF) << 24);
}

// exact fp32 dot — identical chain to the rel_err-0.0 passing rounds
__device__ __forceinline__ float dot64(const float4* __restrict__ a,
                                       const float4* __restrict__ b) {
    float s = 0.0f;
#pragma unroll
    for (int i = 0; i < 16; i++) {
        float4 x = a[i], y = b[i];
        s = fmaf(x.x, y.x, s);
        s = fmaf(x.y, y.y, s);
        s = fmaf(x.z, y.z, s);
        s = fmaf(x.w, y.w, s);
    }
    return s;
}

// ---------------------------------------------------------------------------
// Kernel 1: cc norms, int8-quantized codebook, zero per-run state
// ---------------------------------------------------------------------------
__global__ void vq_prep(const float* __restrict__ cb) {
    int bx = blockIdx.x, t = threadIdx.x;
    if (bx < 256) {
        int e = bx * 256 + t;              // 65536 rows
        g_ccount[e] = 0;
        g_over[e] = 0;
    } else {
        int j = (bx - 256) * 256 + t;      // 1024 codes
        if (j < N_CODE) {
            const float4* p = reinterpret_cast<const float4*>(cb + j * E_DIM);
            float s = 0.0f;
            int q[64];
#pragma unroll
            for (int i = 0; i < 16; i++) {
                float4 v = p[i];
                s = fmaf(v.x, v.x, s);
                s = fmaf(v.y, v.y, s);
                s = fmaf(v.z, v.z, s);
                s = fmaf(v.w, v.w, s);
                q[4 * i + 0] = (int)rintf(v.x * SCALE_E);
                q[4 * i + 1] = (int)rintf(v.y * SCALE_E);
                q[4 * i + 2] = (int)rintf(v.z * SCALE_E);
                q[4 * i + 3] = (int)rintf(v.w * SCALE_E);
            }
            g_cc[j] = s;
            g_counts[j] = 0;
#pragma unroll
            for (int w = 0; w < 16; w++)
                g_cb_i8[j * 16 + w] = pack4(q[4 * w], q[4 * w + 1], q[4 * w + 2], q[4 * w + 3]);
        }
    }
}

// ---------------------------------------------------------------------------
// Kernel 2: DP4A int8 screening. 256 CTAs x 256 threads, 1 row/thread.
//   Whole int8 codebook (64 KB) + cc (4 KB) staged in smem once.
// ---------------------------------------------------------------------------
#define SMEM_SCREEN (N_CODE * 64 + N_CODE * 4)    // 69632 B

__global__ void __launch_bounds__(256, 2)
vq_screen(const float* __restrict__ z) {
    extern __shared__ uint4 sE[];                       // [4096] = 64 KB
    float* scc = reinterpret_cast<float*>(sE + N_CODE * 4);

    const int tid = threadIdx.x;
    const int row = blockIdx.x * 256 + tid;

    // stage codebook + cc (coalesced)
    {
        const uint4* src = reinterpret_cast<const uint4*>(g_cb_i8);
#pragma unroll
        for (int k = 0; k < 16; k++)
            sE[k * 256 + tid] = src[k * 256 + tid];
#pragma unroll
        for (int k = 0; k < 4; k++)
            scc[k * 256 + tid] = g_cc[k * 256 + tid];
    }

    // load z row, quantize to int8 (per-row scale)
    float zr[64];
    {
        const float4* zp = reinterpret_cast<const float4*>(z + (size_t)row * E_DIM);
#pragma unroll
        for (int i = 0; i < 16; i++) {
            float4 v = zp[i];
            zr[4 * i] = v.x; zr[4 * i + 1] = v.y; zr[4 * i + 2] = v.z; zr[4 * i + 3] = v.w;
        }
    }
    float maxa = 1e-20f;
#pragma unroll
    for (int i = 0; i < 64; i++) maxa = fmaxf(maxa, fabsf(zr[i]));
    const float zscale = 127.0f / maxa;
    uint32_t zq[16];
    int S_z = 0;
#pragma unroll
    for (int w = 0; w < 16; w++) {
        int a = (int)rintf(zr[4 * w] * zscale);
        int b = (int)rintf(zr[4 * w + 1] * zscale);
        int c = (int)rintf(zr[4 * w + 2] * zscale);
        int d = (int)rintf(zr[4 * w + 3] * zscale);
        S_z += abs(a) + abs(b) + abs(c) + abs(d);
        zq[w] = pack4(a, b, c, d);
    }
    const float inv = 1.0f / (zscale * SCALE_E);
    const float n2inv = -2.0f * inv;
    // rigorous quantization margin + cross-rounding slack
    const float marg = inv * (8192.0f + (float)S_z) + 1e-4f;

    __syncthreads();

    float rmin = CUDART_INF_F;
    for (int j = 0; j < N_CODE; j++) {
        const uint4 w0 = sE[j * 4 + 0];
        const uint4 w1 = sE[j * 4 + 1];
        const uint4 w2 = sE[j * 4 + 2];
        const uint4 w3 = sE[j * 4 + 3];
        int a0 = 0, a1 = 0, a2 = 0, a3 = 0;           // 4 chains for ILP
        a0 = dp4a(zq[0],  w0.x, a0); a1 = dp4a(zq[1],  w0.y, a1);
        a2 = dp4a(zq[2],  w0.z, a2); a3 = dp4a(zq[3],  w0.w, a3);
        a0 = dp4a(zq[4],  w1.x, a0); a1 = dp4a(zq[5],  w1.y, a1);
        a2 = dp4a(zq[6],  w1.z, a2); a3 = dp4a(zq[7],  w1.w, a3);
        a0 = dp4a(zq[8],  w2.x, a0); a1 = dp4a(zq[9],  w2.y, a1);
        a2 = dp4a(zq[10], w2.z, a2); a3 = dp4a(zq[11], w2.w, a3);
        a0 = dp4a(zq[12], w3.x, a0); a1 = dp4a(zq[13], w3.y, a1);
        a2 = dp4a(zq[14], w3.z, a2); a3 = dp4a(zq[15], w3.w, a3);
        const int acc = (a0 + a1) + (a2 + a3);        // exact int32
        const float t = fmaf(n2inv, (float)acc, scc[j]);
        rmin = fminf(rmin, t);
        if (t <= rmin + marg) {                       // online emission (provably safe)
            int s = atomicAdd(&g_ccount[row], 1);
            if (s < CAP) g_cand[row * CAP + s] = j;
            else g_over[row] = 1;
        }
    }
}

// ---------------------------------------------------------------------------
// Kernel 3: exact fp32 recheck + fused epilogue. One warp per row.
//   argmin (exact, first-index ties), z_q STE write, SSE partial, counts.
// ---------------------------------------------------------------------------
__global__ void __launch_bounds__(256)
vq_recheck(const float* __restrict__ z, const float* __restrict__ cb,
           float* __restrict__ out_idxf, float* __restrict__ out_zq) {
    const int lane = threadIdx.x & 31;
    const int w = threadIdx.x >> 5;
    const int row = blockIdx.x * 8 + w;

    // broadcast-load z row
    float4 zr[16];
    const float4* zp = reinterpret_cast<const float4*>(z + (size_t)row * E_DIM);
#pragma unroll
    for (int i = 0; i < 16; i++) zr[i] = zp[i];

    float zz = 0.0f;
#pragma unroll
    for (int i = 0; i < 16; i++) {
        float4 v = zr[i];
        zz = fmaf(v.x, v.x, zz);
        zz = fmaf(v.y, v.y, zz);
        zz = fmaf(v.z, v.z, zz);
        zz = fmaf(v.w, v.w, zz);
    }

    int n = g_ccount[row];
    bool full = (g_over[row] != 0) || (n > CAP);
    int n_eff = full ? N_CODE : n;

    unsigned long long best = 0xffffffffffffffffull;
    for (int i = lane; i < n_eff; i += 32) {
        int j = full ? i : g_cand[row * CAP + i];
        const float4* ep = reinterpret_cast<const float4*>(cb + (size_t)j * E_DIM);
        float dot = dot64(zr, ep);
        float d = fmaf(-2.0f, dot, zz + __ldg(&g_cc[j]));
        unsigned long long pk =
            ((unsigned long long)__float_as_uint(d) << 32) | (unsigned)j;
        best = min(best, pk);
    }
#pragma unroll
    for (int off = 16; off > 0; off >>= 1)
        best = min(best, __shfl_xor_sync(0xffffffff, best, off));
    const int bi = (int)(best & 0xffffffffu);

    if (lane == 0) {
        g_idx[row] = bi;
        out_idxf[row] = (float)bi;
        atomicAdd(&g_counts[bi], 1);
    }

    // fused epilogue: lane l handles elements 2l, 2l+1 of this row.
    // NOTE: out_zq = out + 1 is only 4-byte aligned -> SCALAR stores only.
    const float2 zf = *reinterpret_cast<const float2*>(z + (size_t)row * E_DIM + 2 * lane);
    const float qx = cb[(size_t)bi * E_DIM + 2 * lane];
    const float qy = cb[(size_t)bi * E_DIM + 2 * lane + 1];
    float dx = qx - zf.x;
    float dy = qy - zf.y;
    float* op = out_zq + (size_t)row * E_DIM + 2 * lane;
    op[0] = zf.x + (qx - zf.x);     // mirror reference STE arithmetic
    op[1] = zf.y + (qy - zf.y);

    float sse = fmaf(dx, dx, dy * dy);
#pragma unroll
    for (int off = 16; off > 0; off >>= 1)
        sse += __shfl_xor_sync(0xffffffff, sse, off);

    __shared__ float wsum[8];
    if (lane == 0) wsum[w] = sse;
    __syncthreads();
    if (threadIdx.x == 0) {
        float s = 0.0f;
#pragma unroll
        for (int k = 0; k < 8; k++) s += wsum[k];
        g_sse_part[blockIdx.x] = s;
    }
}

// ---------------------------------------------------------------------------
// Kernel 4: finalize loss + perplexity
// ---------------------------------------------------------------------------
__global__ void vq_finalize(float* __restrict__ out) {
    __shared__ float red[1024];
    int t = threadIdx.x;

    float s = 0.0f;
#pragma unroll
    for (int k = 0; k < 8; k++) s += g_sse_part[t + k * 1024];
    red[t] = s;
    __syncthreads();
#pragma unroll
    for (int st = 512; st > 0; st >>= 1) {
        if (t < st) red[t] += red[t + st];
        __syncthreads();
    }
    float sse = red[0];
    __syncthreads();

    float c = (float)g_counts[t];
    float em = c * (1.0f / (float)N_VEC);
    red[t] = em * logf(em + 1e-10f);
    __syncthreads();
#pragma unroll
    for (int st = 512; st > 0; st >>= 1) {
        if (t < st) red[t] += red[t + st];
        __syncthreads();
    }
    if (t == 0) {
        float mean = sse * (1.0f / (float)ELEMS);
        out[0] = 1.25f * mean;             // (1 + BETA) * mean((z_q - z)^2)
        out[1 + ELEMS] = expf(-red[0]);    // perplexity
    }
}

// ---------------------------------------------------------------------------
// Launch: out layout = [loss(1) | z_q_st(N*64) | perplexity(1) | idx(N)]
// ---------------------------------------------------------------------------
extern "C" void kernel_launch(void* const* d_in, const int* in_sizes, int n_in,
                              void* d_out, int out_size) {
    const float* z  = (const float*)d_in[0];
    const float* cb = (const float*)d_in[1];
    float* out = (float*)d_out;

    float* out_zq   = out + 1;
    float* out_idxf = out + 2 + ELEMS;

    static bool attr_set = false;
    if (!attr_set) {
        cudaFuncSetAttribute(vq_screen, cudaFuncAttributeMaxDynamicSharedMemorySize,
                             SMEM_SCREEN);
        attr_set = true;
    }

    vq_prep<<<260, 256>>>(cb);
    vq_screen<<<N_VEC / 256, 256, SMEM_SCREEN>>>(z);
    vq_recheck<<<N_VEC / 8, 256>>>(z, cb, out_idxf, out_zq);
    vq_finalize<<<1, 1024>>>(out);
}